// round 4
// baseline (speedup 1.0000x reference)
#include <cuda_runtime.h>
#include <math.h>

// ---------------------------------------------------------------------------
// Problem constants
// ---------------------------------------------------------------------------
#define BSZ     256     // batch
#define KSAMP   64      // MC samples per batch element
#define NPATH   (BSZ*KSAMP)      // 16384 paths
#define L1C     32
#define L2C     31
#define DIMC    3
#define DCH     4       // DIM+1 (time-augmented)
#define LPATH   63
#define STEPS   62      // LPATH-1
#define IN_DIM  159     // L1*(DIM+1)+L2
#define MDIM    93      // L2*DIM
#define MATEL   2976
#define OUT_TOT (MDIM + MATEL)   // 3069 linear outputs
#define SIGDIM  340     // 4+16+64+256
#define NCLS    10

// ---------------------------------------------------------------------------
// Scratch (static __device__ — no allocation)
// ---------------------------------------------------------------------------
__device__ __align__(16) float  g_mean[BSZ * MDIM];          //  95 KB
__device__ __align__(16) float  g_cov [BSZ * MATEL];         // 3.0 MB
__device__ __align__(16) float4 g_dX  [NPATH * STEPS];       // 16.3 MB
__device__ __align__(16) float  g_sig [NPATH * SIGDIM];      // 22.3 MB

// ---------------------------------------------------------------------------
// K1: fused linear  out[o,b] = x[b,:] . W[o,:] + bias[o]
//     o in [0,93) -> mean ; o in [93,3069) -> sqrtCov
//     64x64 tile, 4x4 register blocking, dynamic smem (82 KB)
// ---------------------------------------------------------------------------
__global__ void __launch_bounds__(256) k_linear(
    const float* __restrict__ x,
    const float* __restrict__ Wm, const float* __restrict__ bm,
    const float* __restrict__ Wc, const float* __restrict__ bc)
{
    extern __shared__ float sm[];
    float (*ws)[161] = (float (*)[161])sm;               // 64 x 161
    float (*xs)[161] = (float (*)[161])(sm + 64 * 161);  // 64 x 161

    const int tid = threadIdx.x;
    const int o0 = blockIdx.x * 64;
    const int b0 = blockIdx.y * 64;

    for (int idx = tid; idx < 64 * IN_DIM; idx += 256) {
        int r = idx / IN_DIM;
        int c = idx - r * IN_DIM;
        int o = o0 + r;
        float wv = 0.f;
        if (o < MDIM)          wv = Wm[o * IN_DIM + c];
        else if (o < OUT_TOT)  wv = Wc[(o - MDIM) * IN_DIM + c];
        ws[r][c] = wv;
        xs[r][c] = x[(b0 + r) * IN_DIM + c];
    }
    __syncthreads();

    const int om = (tid & 15) * 4;   // 16 o-groups
    const int bn = (tid >> 4) * 4;   // 16 b-groups

    float acc[4][4];
#pragma unroll
    for (int u = 0; u < 4; u++)
#pragma unroll
        for (int v = 0; v < 4; v++) acc[u][v] = 0.f;

    for (int j = 0; j < IN_DIM; j++) {
        float w0 = ws[om + 0][j], w1 = ws[om + 1][j];
        float w2 = ws[om + 2][j], w3 = ws[om + 3][j];
        float a0 = xs[bn + 0][j], a1 = xs[bn + 1][j];
        float a2 = xs[bn + 2][j], a3 = xs[bn + 3][j];
        acc[0][0] = fmaf(w0, a0, acc[0][0]); acc[0][1] = fmaf(w0, a1, acc[0][1]);
        acc[0][2] = fmaf(w0, a2, acc[0][2]); acc[0][3] = fmaf(w0, a3, acc[0][3]);
        acc[1][0] = fmaf(w1, a0, acc[1][0]); acc[1][1] = fmaf(w1, a1, acc[1][1]);
        acc[1][2] = fmaf(w1, a2, acc[1][2]); acc[1][3] = fmaf(w1, a3, acc[1][3]);
        acc[2][0] = fmaf(w2, a0, acc[2][0]); acc[2][1] = fmaf(w2, a1, acc[2][1]);
        acc[2][2] = fmaf(w2, a2, acc[2][2]); acc[2][3] = fmaf(w2, a3, acc[2][3]);
        acc[3][0] = fmaf(w3, a0, acc[3][0]); acc[3][1] = fmaf(w3, a1, acc[3][1]);
        acc[3][2] = fmaf(w3, a2, acc[3][2]); acc[3][3] = fmaf(w3, a3, acc[3][3]);
    }

#pragma unroll
    for (int u = 0; u < 4; u++) {
        int o = o0 + om + u;
        if (o >= OUT_TOT) continue;
        float bias = (o < MDIM) ? bm[o] : bc[o - MDIM];
#pragma unroll
        for (int v = 0; v < 4; v++) {
            int b = b0 + bn + v;
            float val = acc[u][v] + bias;
            if (o < MDIM) g_mean[b * MDIM + o] = val;
            else          g_cov [b * MATEL + (o - MDIM)] = val;
        }
    }
}

// ---------------------------------------------------------------------------
// K2: banded sqrt-cov matvec (newV = M*eps + mean) + path increments dX.
//     One block per batch element. Band structure derived analytically:
//     M block (r,c), c<=r, each 3x3 block lower-triangular; pair index
//     base(off)=off*31-off*(off-1)/2 + c, tril-index tb = dd*(dd+1)/2 + tc.
// ---------------------------------------------------------------------------
__device__ __forceinline__ int order_of(int p) {
    // interleave: [0,32,1,33,...,30,62,31]
    return (p == 62) ? 31 : ((p & 1) ? 32 + (p >> 1) : (p >> 1));
}

__global__ void __launch_bounds__(256) k_path(
    const float* __restrict__ x, const float* __restrict__ eps)
{
    const int b = blockIdx.x;
    const int tid = threadIdx.x;

    __shared__ float cov_s[MATEL];
    __shared__ float nv[MDIM * KSAMP];   // newV [i][k]
    __shared__ float xs[IN_DIM + 1];
    __shared__ float mean_s[MDIM + 3];

    for (int idx = tid; idx < MATEL; idx += 256) cov_s[idx] = g_cov[b * MATEL + idx];
    if (tid < IN_DIM) xs[tid] = x[b * IN_DIM + tid];
    if (tid < MDIM)   mean_s[tid] = g_mean[b * MDIM + tid];
    __syncthreads();

    const int k   = tid & 63;
    const int grp = tid >> 6;
    const float* epsb = eps + b * (MDIM * KSAMP) + k;

    for (int i = grp; i < MDIM; i += 4) {
        int r  = i / 3;
        int dd = i - 3 * r;
        int tb = (dd * (dd + 1)) >> 1;
        float acc = mean_s[i];
        for (int c = 0; c <= r; c++) {
            int off = r - c;
            int pairIdx = off * 31 - ((off * (off - 1)) >> 1) + c;
            const float* cv = cov_s + pairIdx * 6 + tb;
            const float* ep = epsb + c * 3 * KSAMP;
            float s = cv[0] * ep[0];
            if (dd >= 1) s = fmaf(cv[1], ep[KSAMP], s);
            if (dd == 2) s = fmaf(cv[2], ep[2 * KSAMP], s);
            acc += s;
        }
        nv[i * KSAMP + k] = acc;
    }
    __syncthreads();

    float* gx = ((float*)g_dX) + b * (KSAMP * STEPS * 4);
    for (int idx = tid; idx < KSAMP * STEPS * 4; idx += 256) {
        int d    = idx & 3;
        int rest = idx >> 2;
        int p    = rest % STEPS;
        int kk   = rest / STEPS;

        // value of path point q, channel d
        int o1 = order_of(p + 1);
        int o0 = order_of(p);
        float v1, v0;
        if (d == 3) { v1 = xs[96 + o1]; v0 = xs[96 + o0]; }
        else {
            v1 = (o1 < L1C) ? xs[o1 * 3 + d] : nv[((o1 - L1C) * 3 + d) * KSAMP + kk];
            v0 = (o0 < L1C) ? xs[o0 * 3 + d] : nv[((o0 - L1C) * 3 + d) * KSAMP + kk];
        }
        gx[idx] = v1 - v0;
    }
}

// ---------------------------------------------------------------------------
// K3: truncated (level 4) signature via Chen's identity + tensor normalization.
//     4 threads per path, split by leading tensor index i = lane%4.
//     Per-thread state: S4[64], S3[16], S2[4], S1  (registers).
//     Factorized update (e_k = dx^(x)k / k!):
//       T4[i,jkl] = S4 + (S3[jk] + (dx_i/12) e2[jk]) * dx_l
//                      + (S2[j]  + (S1/3)  dx_j   ) * e2[kl]
//       T3[i,jk]  = S3 + (S1 + dx_i/3) e2[jk] + S2[j] dx_k
//       T2[i,j]   = S2 + (S1 + dx_i/2) dx_j
//       T1[i]     = S1 + dx_i
// ---------------------------------------------------------------------------
__global__ void __launch_bounds__(128, 3) k_sig()
{
    const int gt   = blockIdx.x * 128 + threadIdx.x;
    const int path = gt >> 2;
    const int i    = gt & 3;

    const float4* dx4 = g_dX + path * STEPS;

    float S1 = 0.f;
    float S2[4]  = {0.f, 0.f, 0.f, 0.f};
    float S3[16];
    float S4[64];
#pragma unroll
    for (int t = 0; t < 16; t++) S3[t] = 0.f;
#pragma unroll
    for (int t = 0; t < 64; t++) S4[t] = 0.f;

    for (int p = 0; p < STEPS; p++) {
        float4 v = __ldg(&dx4[p]);
        float dxa[4] = {v.x, v.y, v.z, v.w};
        float dxi = (i == 0) ? v.x : (i == 1) ? v.y : (i == 2) ? v.z : v.w;

        float e2[16];
#pragma unroll
        for (int j = 0; j < 4; j++) {
            float hj = 0.5f * dxa[j];
#pragma unroll
            for (int kk = 0; kk < 4; kk++) e2[j * 4 + kk] = hj * dxa[kk];
        }

        float q = dxi * (1.f / 12.f);
        float A[16];
#pragma unroll
        for (int t = 0; t < 16; t++) A[t] = fmaf(q, e2[t], S3[t]);

        float s13 = S1 * (1.f / 3.f);
        float c[4];
#pragma unroll
        for (int j = 0; j < 4; j++) c[j] = fmaf(s13, dxa[j], S2[j]);

#pragma unroll
        for (int j = 0; j < 4; j++)
#pragma unroll
            for (int kk = 0; kk < 4; kk++) {
                float a = A[j * 4 + kk];
                float cj = c[j];
#pragma unroll
                for (int l = 0; l < 4; l++) {
                    int idx = j * 16 + kk * 4 + l;
                    S4[idx] = fmaf(a, dxa[l], fmaf(cj, e2[kk * 4 + l], S4[idx]));
                }
            }

        float g = fmaf(1.f / 3.f, dxi, S1);
#pragma unroll
        for (int j = 0; j < 4; j++)
#pragma unroll
            for (int kk = 0; kk < 4; kk++)
                S3[j * 4 + kk] = fmaf(g, e2[j * 4 + kk], fmaf(S2[j], dxa[kk], S3[j * 4 + kk]));

        float h = fmaf(0.5f, dxi, S1);
#pragma unroll
        for (int j = 0; j < 4; j++) S2[j] = fmaf(h, dxa[j], S2[j]);

        S1 += dxi;
    }

    // ---- norms (reduce across the 4 lanes of this path) ----
    float n1 = S1 * S1;
    float n2 = 0.f, n3 = 0.f, n4 = 0.f;
#pragma unroll
    for (int t = 0; t < 4; t++)  n2 = fmaf(S2[t], S2[t], n2);
#pragma unroll
    for (int t = 0; t < 16; t++) n3 = fmaf(S3[t], S3[t], n3);
#pragma unroll
    for (int t = 0; t < 64; t++) n4 = fmaf(S4[t], S4[t], n4);

    n1 += __shfl_xor_sync(0xffffffffu, n1, 1);
    n1 += __shfl_xor_sync(0xffffffffu, n1, 2);
    n2 += __shfl_xor_sync(0xffffffffu, n2, 1);
    n2 += __shfl_xor_sync(0xffffffffu, n2, 2);
    n3 += __shfl_xor_sync(0xffffffffu, n3, 1);
    n3 += __shfl_xor_sync(0xffffffffu, n3, 2);
    n4 += __shfl_xor_sync(0xffffffffu, n4, 1);
    n4 += __shfl_xor_sync(0xffffffffu, n4, 2);

    float norm2 = 1.f + n1 + n2 + n3 + n4;
    // phi with C=4, A=1:  x<=4 -> x ; else 4 + 16*(0.25 - 1/x) = 8 - 16/x
    float psi = (norm2 <= 4.f) ? norm2 : (8.f - 16.f / norm2);

    float lo = 0.f, hi = 1.f;
#pragma unroll 4
    for (int it = 0; it < 40; it++) {
        float mid = 0.5f * (lo + hi);
        float m2 = mid * mid;
        float val = fmaf(m2, fmaf(m2, fmaf(m2, fmaf(m2, n4, n3), n2), n1), 1.f);
        bool pos = val > psi;
        hi = pos ? mid : hi;
        lo = pos ? lo : mid;
    }
    float lam = 0.5f * (lo + hi);
    float l2 = lam * lam, l3 = l2 * lam, l4 = l2 * l2;

    float* sp = g_sig + path * SIGDIM;
    sp[i] = S1 * lam;                                    // level 1 at [0,4)
    *reinterpret_cast<float4*>(sp + 4 + i * 4) =         // level 2 at [4,20)
        make_float4(S2[0] * l2, S2[1] * l2, S2[2] * l2, S2[3] * l2);
#pragma unroll
    for (int t = 0; t < 4; t++)                          // level 3 at [20,84)
        reinterpret_cast<float4*>(sp + 20 + i * 16)[t] =
            make_float4(S3[4*t] * l3, S3[4*t+1] * l3, S3[4*t+2] * l3, S3[4*t+3] * l3);
#pragma unroll
    for (int t = 0; t < 16; t++)                         // level 4 at [84,340)
        reinterpret_cast<float4*>(sp + 84 + i * 64)[t] =
            make_float4(S4[4*t] * l4, S4[4*t+1] * l4, S4[4*t+2] * l4, S4[4*t+3] * l4);
}

// ---------------------------------------------------------------------------
// K4: mean over K samples, final linear, log_softmax.  One block per b.
// ---------------------------------------------------------------------------
__global__ void __launch_bounds__(320) k_final(
    const float* __restrict__ Wf, const float* __restrict__ bf,
    float* __restrict__ out)
{
    const int b = blockIdx.x;
    const int tid = threadIdx.x;
    __shared__ float ss[SIGDIM + 4];
    __shared__ float lg[NCLS + 2];
    __shared__ float s_lse;

    for (int v = tid; v < SIGDIM; v += 320) {
        const float* p = g_sig + (size_t)b * KSAMP * SIGDIM + v;
        float s0 = 0.f, s1 = 0.f, s2 = 0.f, s3 = 0.f;
#pragma unroll
        for (int kk = 0; kk < KSAMP; kk += 4) {
            s0 += p[(kk + 0) * SIGDIM];
            s1 += p[(kk + 1) * SIGDIM];
            s2 += p[(kk + 2) * SIGDIM];
            s3 += p[(kk + 3) * SIGDIM];
        }
        ss[v] = ((s0 + s1) + (s2 + s3)) * (1.f / (float)KSAMP);
    }
    __syncthreads();

    const int cls = tid >> 5;     // 10 warps -> 10 classes
    const int lane = tid & 31;
    float part = 0.f;
    for (int v = lane; v < SIGDIM; v += 32)
        part = fmaf(ss[v], Wf[cls * SIGDIM + v], part);
#pragma unroll
    for (int o = 16; o; o >>= 1) part += __shfl_xor_sync(0xffffffffu, part, o);
    if (lane == 0) lg[cls] = part + bf[cls];
    __syncthreads();

    if (tid == 0) {
        float mx = lg[0];
        for (int c = 1; c < NCLS; c++) mx = fmaxf(mx, lg[c]);
        float se = 0.f;
        for (int c = 0; c < NCLS; c++) se += expf(lg[c] - mx);
        s_lse = mx + logf(se);
    }
    __syncthreads();
    if (tid < NCLS) out[b * NCLS + tid] = lg[tid] - s_lse;
}

// ---------------------------------------------------------------------------
// launch
// ---------------------------------------------------------------------------
extern "C" void kernel_launch(void* const* d_in, const int* in_sizes, int n_in,
                              void* d_out, int out_size)
{
    const float* x   = (const float*)d_in[0];
    const float* Wm  = (const float*)d_in[1];
    const float* bm  = (const float*)d_in[2];
    const float* Wc  = (const float*)d_in[3];
    const float* bc  = (const float*)d_in[4];
    const float* Wf  = (const float*)d_in[5];
    const float* bf  = (const float*)d_in[6];
    const float* eps = (const float*)d_in[7];
    float* out = (float*)d_out;

    const int smem1 = 2 * 64 * 161 * (int)sizeof(float);   // 82432 B
    cudaFuncSetAttribute(k_linear, cudaFuncAttributeMaxDynamicSharedMemorySize, smem1);

    dim3 g1((OUT_TOT + 63) / 64, BSZ / 64);
    k_linear<<<g1, 256, smem1>>>(x, Wm, bm, Wc, bc);
    k_path  <<<BSZ, 256>>>(x, eps);
    k_sig   <<<NPATH * 4 / 128, 128>>>();
    k_final <<<BSZ, 320>>>(Wf, bf, out);
}

// round 5
// speedup vs baseline: 1.2580x; 1.2580x over previous
#include <cuda_runtime.h>
#include <math.h>

// ---------------------------------------------------------------------------
// Problem constants
// ---------------------------------------------------------------------------
#define BSZ     256
#define KSAMP   64
#define NPATH   (BSZ*KSAMP)      // 16384 paths
#define L1C     32
#define L2C     31
#define LPATH   63
#define STEPS   62
#define IN_DIM  159
#define MDIM    93
#define MATEL   2976
#define OUT_TOT (MDIM + MATEL)   // 3069
#define SIGDIM  340
#define NCLS    10

// ---------------------------------------------------------------------------
// Scratch (static __device__ — no allocation)
// ---------------------------------------------------------------------------
__device__ __align__(16) float  g_mean[BSZ * MDIM];
__device__ __align__(16) float  g_cov [BSZ * MATEL];
__device__ __align__(16) float4 g_dX  [NPATH * STEPS];       // 16.3 MB
__device__ __align__(16) float  g_part[512 * SIGDIM];        // 0.7 MB partial sums

// ---------------------------------------------------------------------------
// K1: fused linear. 64x64 tile, 4x4 register blocking with stride-16 rows
//     (conflict-free LDS: row stride 161 is odd, 16-row step -> 16 banks).
// ---------------------------------------------------------------------------
__global__ void __launch_bounds__(256) k_linear(
    const float* __restrict__ x,
    const float* __restrict__ Wm, const float* __restrict__ bm,
    const float* __restrict__ Wc, const float* __restrict__ bc)
{
    extern __shared__ float sm[];
    float (*ws)[161] = (float (*)[161])sm;               // 64 x 161
    float (*xs)[161] = (float (*)[161])(sm + 64 * 161);  // 64 x 161

    const int tid = threadIdx.x;
    const int o0 = blockIdx.x * 64;
    const int b0 = blockIdx.y * 64;

    for (int idx = tid; idx < 64 * IN_DIM; idx += 256) {
        int r = idx / IN_DIM;
        int c = idx - r * IN_DIM;
        int o = o0 + r;
        float wv = 0.f;
        if (o < MDIM)          wv = Wm[o * IN_DIM + c];
        else if (o < OUT_TOT)  wv = Wc[(o - MDIM) * IN_DIM + c];
        ws[r][c] = wv;
        xs[r][c] = x[(b0 + r) * IN_DIM + c];
    }
    __syncthreads();

    const int om = tid & 15;     // row r, r+16, r+32, r+48
    const int bn = tid >> 4;

    float acc[4][4];
#pragma unroll
    for (int u = 0; u < 4; u++)
#pragma unroll
        for (int v = 0; v < 4; v++) acc[u][v] = 0.f;

    for (int j = 0; j < IN_DIM; j++) {
        float w0 = ws[om +  0][j], w1 = ws[om + 16][j];
        float w2 = ws[om + 32][j], w3 = ws[om + 48][j];
        float a0 = xs[bn +  0][j], a1 = xs[bn + 16][j];
        float a2 = xs[bn + 32][j], a3 = xs[bn + 48][j];
        acc[0][0] = fmaf(w0, a0, acc[0][0]); acc[0][1] = fmaf(w0, a1, acc[0][1]);
        acc[0][2] = fmaf(w0, a2, acc[0][2]); acc[0][3] = fmaf(w0, a3, acc[0][3]);
        acc[1][0] = fmaf(w1, a0, acc[1][0]); acc[1][1] = fmaf(w1, a1, acc[1][1]);
        acc[1][2] = fmaf(w1, a2, acc[1][2]); acc[1][3] = fmaf(w1, a3, acc[1][3]);
        acc[2][0] = fmaf(w2, a0, acc[2][0]); acc[2][1] = fmaf(w2, a1, acc[2][1]);
        acc[2][2] = fmaf(w2, a2, acc[2][2]); acc[2][3] = fmaf(w2, a3, acc[2][3]);
        acc[3][0] = fmaf(w3, a0, acc[3][0]); acc[3][1] = fmaf(w3, a1, acc[3][1]);
        acc[3][2] = fmaf(w3, a2, acc[3][2]); acc[3][3] = fmaf(w3, a3, acc[3][3]);
    }

#pragma unroll
    for (int u = 0; u < 4; u++) {
        int o = o0 + om + 16 * u;
        if (o >= OUT_TOT) continue;
        float bias = (o < MDIM) ? bm[o] : bc[o - MDIM];
#pragma unroll
        for (int v = 0; v < 4; v++) {
            int b = b0 + bn + 16 * v;
            float val = acc[u][v] + bias;
            if (o < MDIM) g_mean[b * MDIM + o] = val;
            else          g_cov [b * MATEL + (o - MDIM)] = val;
        }
    }
}

// ---------------------------------------------------------------------------
// K2: banded sqrt-cov matvec + path increments dX (unchanged).
// ---------------------------------------------------------------------------
__device__ __forceinline__ int order_of(int p) {
    return (p == 62) ? 31 : ((p & 1) ? 32 + (p >> 1) : (p >> 1));
}

__global__ void __launch_bounds__(256) k_path(
    const float* __restrict__ x, const float* __restrict__ eps)
{
    const int b = blockIdx.x;
    const int tid = threadIdx.x;

    __shared__ float cov_s[MATEL];
    __shared__ float nv[MDIM * KSAMP];
    __shared__ float xs[IN_DIM + 1];
    __shared__ float mean_s[MDIM + 3];

    for (int idx = tid; idx < MATEL; idx += 256) cov_s[idx] = g_cov[b * MATEL + idx];
    if (tid < IN_DIM) xs[tid] = x[b * IN_DIM + tid];
    if (tid < MDIM)   mean_s[tid] = g_mean[b * MDIM + tid];
    __syncthreads();

    const int k   = tid & 63;
    const int grp = tid >> 6;
    const float* epsb = eps + b * (MDIM * KSAMP) + k;

    for (int i = grp; i < MDIM; i += 4) {
        int r  = i / 3;
        int dd = i - 3 * r;
        int tb = (dd * (dd + 1)) >> 1;
        float acc = mean_s[i];
        for (int c = 0; c <= r; c++) {
            int off = r - c;
            int pairIdx = off * 31 - ((off * (off - 1)) >> 1) + c;
            const float* cv = cov_s + pairIdx * 6 + tb;
            const float* ep = epsb + c * 3 * KSAMP;
            float s = cv[0] * ep[0];
            if (dd >= 1) s = fmaf(cv[1], ep[KSAMP], s);
            if (dd == 2) s = fmaf(cv[2], ep[2 * KSAMP], s);
            acc += s;
        }
        nv[i * KSAMP + k] = acc;
    }
    __syncthreads();

    float* gx = ((float*)g_dX) + b * (KSAMP * STEPS * 4);
    for (int idx = tid; idx < KSAMP * STEPS * 4; idx += 256) {
        int d    = idx & 3;
        int rest = idx >> 2;
        int p    = rest % STEPS;
        int kk   = rest / STEPS;
        int o1 = order_of(p + 1);
        int o0 = order_of(p);
        float v1, v0;
        if (d == 3) { v1 = xs[96 + o1]; v0 = xs[96 + o0]; }
        else {
            v1 = (o1 < L1C) ? xs[o1 * 3 + d] : nv[((o1 - L1C) * 3 + d) * KSAMP + kk];
            v0 = (o0 < L1C) ? xs[o0 * 3 + d] : nv[((o0 - L1C) * 3 + d) * KSAMP + kk];
        }
        gx[idx] = v1 - v0;
    }
}

// ---------------------------------------------------------------------------
// K3: signature + normalization + in-block reduction over 32 paths.
//     Fully folded Chen step (~112 FMA/step):
//       w    = dx_i/24 + S1/6
//       u[j] = w*dx_j + 0.5*S2[j]
//       B[jk]= S3[jk] + u[j]*dx_k
//       S4[jkl] += B[jk]*dx_l
//       f[j] = (0.5*S1 + dx_i/6)*dx_j + S2[j]
//       S3[jk] += f[j]*dx_k
//       S2[j]  += (S1 + 0.5*dx_i)*dx_j
//       S1     += dx_i
//     (all RHS use pre-step state; B,f are materialized before updates)
//     grid=512: block bh covers paths [bh*32, bh*32+32) (half a batch elem).
// ---------------------------------------------------------------------------
#define BUFW 344   // padded row (multiple of 4, odd/32-coprime enough)
__global__ void __launch_bounds__(128, 3) k_sig()
{
    const int tid  = threadIdx.x;
    const int pid  = tid >> 2;              // path-in-block 0..31
    const int i    = tid & 3;               // leading tensor index
    const int path = blockIdx.x * 32 + pid;

    __shared__ float buf[32][BUFW];

    const float4* dx4 = g_dX + path * STEPS;

    float S1 = 0.f;
    float S2[4]  = {0.f, 0.f, 0.f, 0.f};
    float S3[16];
    float S4[64];
#pragma unroll
    for (int t = 0; t < 16; t++) S3[t] = 0.f;
#pragma unroll
    for (int t = 0; t < 64; t++) S4[t] = 0.f;

    float4 v = __ldg(&dx4[0]);
    for (int p = 0; p < STEPS; p++) {
        float4 vn = (p + 1 < STEPS) ? __ldg(&dx4[p + 1]) : v;
        float dxa[4] = {v.x, v.y, v.z, v.w};
        float dxi = (i == 0) ? v.x : (i == 1) ? v.y : (i == 2) ? v.z : v.w;

        // level-4 folded term
        float w = fmaf(dxi, 1.f / 24.f, S1 * (1.f / 6.f));
        float u[4], B[16];
#pragma unroll
        for (int j = 0; j < 4; j++) u[j] = fmaf(w, dxa[j], 0.5f * S2[j]);
#pragma unroll
        for (int j = 0; j < 4; j++)
#pragma unroll
            for (int kk = 0; kk < 4; kk++)
                B[j * 4 + kk] = fmaf(u[j], dxa[kk], S3[j * 4 + kk]);
#pragma unroll
        for (int j = 0; j < 4; j++)
#pragma unroll
            for (int kk = 0; kk < 4; kk++) {
                float b = B[j * 4 + kk];
#pragma unroll
                for (int l = 0; l < 4; l++)
                    S4[j * 16 + kk * 4 + l] = fmaf(b, dxa[l], S4[j * 16 + kk * 4 + l]);
            }

        // level-3 folded term
        float g2 = fmaf(dxi, 1.f / 6.f, 0.5f * S1);
        float f[4];
#pragma unroll
        for (int j = 0; j < 4; j++) f[j] = fmaf(g2, dxa[j], S2[j]);
#pragma unroll
        for (int j = 0; j < 4; j++)
#pragma unroll
            for (int kk = 0; kk < 4; kk++)
                S3[j * 4 + kk] = fmaf(f[j], dxa[kk], S3[j * 4 + kk]);

        // level-2, level-1
        float h = fmaf(0.5f, dxi, S1);
#pragma unroll
        for (int j = 0; j < 4; j++) S2[j] = fmaf(h, dxa[j], S2[j]);
        S1 += dxi;
        v = vn;
    }

    // ---- norms across the 4 lanes of this path ----
    float n1 = S1 * S1;
    float n2 = 0.f, n3 = 0.f, n4 = 0.f;
#pragma unroll
    for (int t = 0; t < 4; t++)  n2 = fmaf(S2[t], S2[t], n2);
#pragma unroll
    for (int t = 0; t < 16; t++) n3 = fmaf(S3[t], S3[t], n3);
#pragma unroll
    for (int t = 0; t < 64; t++) n4 = fmaf(S4[t], S4[t], n4);

    n1 += __shfl_xor_sync(0xffffffffu, n1, 1);
    n1 += __shfl_xor_sync(0xffffffffu, n1, 2);
    n2 += __shfl_xor_sync(0xffffffffu, n2, 1);
    n2 += __shfl_xor_sync(0xffffffffu, n2, 2);
    n3 += __shfl_xor_sync(0xffffffffu, n3, 1);
    n3 += __shfl_xor_sync(0xffffffffu, n3, 2);
    n4 += __shfl_xor_sync(0xffffffffu, n4, 1);
    n4 += __shfl_xor_sync(0xffffffffu, n4, 2);

    float norm2 = 1.f + n1 + n2 + n3 + n4;
    float psi = (norm2 <= 4.f) ? norm2 : (8.f - 16.f / norm2);

    float lo = 0.f, hi = 1.f;
#pragma unroll 4
    for (int it = 0; it < 40; it++) {
        float mid = 0.5f * (lo + hi);
        float m2 = mid * mid;
        float val = fmaf(m2, fmaf(m2, fmaf(m2, fmaf(m2, n4, n3), n2), n1), 1.f);
        bool pos = val > psi;
        hi = pos ? mid : hi;
        lo = pos ? lo : mid;
    }
    float lam = 0.5f * (lo + hi);
    float l2 = lam * lam, l3 = l2 * lam, l4 = l2 * l2;

    // ---- write this path's full scaled signature into smem buf ----
    float* row = buf[pid];
    row[i] = S1 * lam;
    *reinterpret_cast<float4*>(row + 4 + i * 4) =
        make_float4(S2[0] * l2, S2[1] * l2, S2[2] * l2, S2[3] * l2);
#pragma unroll
    for (int t = 0; t < 4; t++)
        reinterpret_cast<float4*>(row + 20 + i * 16)[t] =
            make_float4(S3[4*t] * l3, S3[4*t+1] * l3, S3[4*t+2] * l3, S3[4*t+3] * l3);
#pragma unroll
    for (int t = 0; t < 16; t++)
        reinterpret_cast<float4*>(row + 84 + i * 64)[t] =
            make_float4(S4[4*t] * l4, S4[4*t+1] * l4, S4[4*t+2] * l4, S4[4*t+3] * l4);
    __syncthreads();

    // ---- reduce over the 32 paths -> one partial vector for this block ----
    float* gp = g_part + blockIdx.x * SIGDIM;
    for (int vv = tid; vv < SIGDIM; vv += 128) {
        float s = 0.f;
#pragma unroll
        for (int pp = 0; pp < 32; pp += 4)
            s += (buf[pp][vv] + buf[pp + 1][vv]) + (buf[pp + 2][vv] + buf[pp + 3][vv]);
        gp[vv] = s;
    }
}

// ---------------------------------------------------------------------------
// K4: combine 2 partials -> mean, final linear, log_softmax. One block per b.
// ---------------------------------------------------------------------------
__global__ void __launch_bounds__(320) k_final(
    const float* __restrict__ Wf, const float* __restrict__ bf,
    float* __restrict__ out)
{
    const int b = blockIdx.x;
    const int tid = threadIdx.x;
    __shared__ float ss[SIGDIM + 4];
    __shared__ float lg[NCLS + 2];
    __shared__ float s_lse;

    const float* p0 = g_part + (2 * b) * SIGDIM;
    const float* p1 = g_part + (2 * b + 1) * SIGDIM;
    for (int vv = tid; vv < SIGDIM; vv += 320)
        ss[vv] = (p0[vv] + p1[vv]) * (1.f / (float)KSAMP);
    __syncthreads();

    const int cls = tid >> 5;
    const int lane = tid & 31;
    float part = 0.f;
    for (int vv = lane; vv < SIGDIM; vv += 32)
        part = fmaf(ss[vv], Wf[cls * SIGDIM + vv], part);
#pragma unroll
    for (int o = 16; o; o >>= 1) part += __shfl_xor_sync(0xffffffffu, part, o);
    if (lane == 0) lg[cls] = part + bf[cls];
    __syncthreads();

    if (tid == 0) {
        float mx = lg[0];
        for (int c = 1; c < NCLS; c++) mx = fmaxf(mx, lg[c]);
        float se = 0.f;
        for (int c = 0; c < NCLS; c++) se += expf(lg[c] - mx);
        s_lse = mx + logf(se);
    }
    __syncthreads();
    if (tid < NCLS) out[b * NCLS + tid] = lg[tid] - s_lse;
}

// ---------------------------------------------------------------------------
// launch
// ---------------------------------------------------------------------------
extern "C" void kernel_launch(void* const* d_in, const int* in_sizes, int n_in,
                              void* d_out, int out_size)
{
    const float* x   = (const float*)d_in[0];
    const float* Wm  = (const float*)d_in[1];
    const float* bm  = (const float*)d_in[2];
    const float* Wc  = (const float*)d_in[3];
    const float* bc  = (const float*)d_in[4];
    const float* Wf  = (const float*)d_in[5];
    const float* bf  = (const float*)d_in[6];
    const float* eps = (const float*)d_in[7];
    float* out = (float*)d_out;

    const int smem1 = 2 * 64 * 161 * (int)sizeof(float);
    cudaFuncSetAttribute(k_linear, cudaFuncAttributeMaxDynamicSharedMemorySize, smem1);

    dim3 g1((OUT_TOT + 63) / 64, BSZ / 64);
    k_linear<<<g1, 256, smem1>>>(x, Wm, bm, Wc, bc);
    k_path  <<<BSZ, 256>>>(x, eps);
    k_sig   <<<512, 128>>>();
    k_final <<<BSZ, 320>>>(Wf, bf, out);
}